// round 15
// baseline (speedup 1.0000x reference)
#include <cuda_runtime.h>
#include <cuda_fp16.h>
#include <mma.h>
#include <cstdint>

using namespace nvcuda;

#define NMAX 100000
#define EMAX 1600000
#define KDIM 128
#define SCAN_ITEMS 1024
#define SCAN_NBLK ((NMAX + SCAN_ITEMS - 1) / SCAN_ITEMS)

// -------- scratch (no allocations allowed; referenced directly from kernels) --------
__device__ __align__(16) float  g_deg[NMAX];
__device__ __align__(16) float  g_dinv[NMAX];
__device__ __align__(16) int    g_cnt[NMAX];
__device__ __align__(16) int    g_cur[NMAX];
__device__ __align__(16) int    g_rowptr[NMAX + 1];
__device__ __align__(16) int    g_bsum[SCAN_NBLK];
__device__ __align__(16) int    g_boff[SCAN_NBLK + 1];
__device__ __align__(16) int    g_col[EMAX];
__device__ __align__(16) float  g_val[EMAX];
__device__ __align__(16) __half g_hh[(size_t)NMAX * 128];   // fp16 hidden (GEMM out, agg in)
__device__ __align__(16) __half g_act[(size_t)NMAX * 128];  // fp16 activations (agg out, GEMM in)
__device__ __align__(16) __half g_xh[(size_t)NMAX * 128];   // fp16 copy of input x
__device__ __align__(16) __half g_w1h[KDIM * 128];
__device__ __align__(16) __half g_w2h[KDIM * 128];
__device__ __align__(16) __half g_w3h[KDIM * 64];

struct __align__(8)  half2x2 { __half2 a, b; };
struct __align__(16) half2x4 { __half2 a, b, c, d; };

// ---------------- fp32 -> fp16 conversion (half2 granularity) ----------------
__global__ void f2h_kernel(const float* __restrict__ in, __half* __restrict__ out, int n2) {
    int i = blockIdx.x * blockDim.x + threadIdx.x;
    if (i < n2) {
        float2 v = ((const float2*)in)[i];
        ((__half2*)out)[i] = __floats2half2_rn(v.x, v.y);
    }
}

// ---------------- degree / histogram init ----------------
__global__ void deg_init_kernel(int n) {
    int i = blockIdx.x * blockDim.x + threadIdx.x;
    if (i < n) { g_deg[i] = 1.0f; g_cnt[i] = 0; }  // self-loop weight 1
}

__global__ void deg_acc_kernel(const int* __restrict__ dst,
                               const float* __restrict__ ew, int E, int n) {
    int e = blockIdx.x * blockDim.x + threadIdx.x;
    if (e < E) {
        int d = dst[e];
        if ((unsigned)d < (unsigned)n) {
            atomicAdd(&g_deg[d], ew[e]);
            atomicAdd(&g_cnt[d], 1);
        }
    }
}

__global__ void dinv_kernel(int n) {
    int i = blockIdx.x * blockDim.x + threadIdx.x;
    if (i < n) {
        float d = g_deg[i];
        g_dinv[i] = d > 0.f ? rsqrtf(d) : 0.f;
    }
}

// ---------------- 3-phase grid-wide exclusive scan: cnt -> rowptr, cur ----------------
__global__ void scan_partial_kernel(int n) {
    __shared__ int sm[256];
    int t = threadIdx.x;
    int base = blockIdx.x * SCAN_ITEMS;
    int s = 0;
    #pragma unroll
    for (int i = 0; i < SCAN_ITEMS / 256; i++) {
        int idx = base + i * 256 + t;
        if (idx < n) s += g_cnt[idx];
    }
    sm[t] = s;
    __syncthreads();
    #pragma unroll
    for (int off = 128; off > 0; off >>= 1) {
        if (t < off) sm[t] += sm[t + off];
        __syncthreads();
    }
    if (t == 0) g_bsum[blockIdx.x] = sm[0];
}

__global__ void scan_blocks_kernel(int nblk, int n) {
    __shared__ int sm[128];
    int t = threadIdx.x;
    sm[t] = (t < nblk) ? g_bsum[t] : 0;
    __syncthreads();
    for (int off = 1; off < 128; off <<= 1) {
        int v = (t >= off) ? sm[t - off] : 0;
        __syncthreads();
        sm[t] += v;
        __syncthreads();
    }
    if (t < nblk) g_boff[t] = (t == 0) ? 0 : sm[t - 1];
    if (t == nblk - 1) {
        g_boff[nblk] = sm[t];
        g_rowptr[n] = sm[t];
    }
}

__global__ void scan_final_kernel(int n) {
    constexpr int IPT = SCAN_ITEMS / 256;
    __shared__ int sm[256];
    int t = threadIdx.x;
    int base = blockIdx.x * SCAN_ITEMS + t * IPT;

    int v[IPT];
    int s = 0;
    #pragma unroll
    for (int i = 0; i < IPT; i++) {
        int idx = base + i;
        v[i] = (idx < n) ? g_cnt[idx] : 0;
        s += v[i];
    }
    sm[t] = s;
    __syncthreads();
    for (int off = 1; off < 256; off <<= 1) {
        int u = (t >= off) ? sm[t - off] : 0;
        __syncthreads();
        sm[t] += u;
        __syncthreads();
    }
    int run = g_boff[blockIdx.x] + ((t == 0) ? 0 : sm[t - 1]);
    #pragma unroll
    for (int i = 0; i < IPT; i++) {
        int idx = base + i;
        if (idx < n) {
            g_rowptr[idx] = run;
            g_cur[idx] = run;
            run += v[i];
        }
    }
}

// ---------------- scatter edges into CSR (col + precomputed norm) ----------------
__global__ void scatter_kernel(const int* __restrict__ src,
                               const int* __restrict__ dst,
                               const float* __restrict__ ew, int E, int n) {
    int e = blockIdx.x * blockDim.x + threadIdx.x;
    if (e >= E) return;
    int s = src[e];
    int d = dst[e];
    if ((unsigned)s >= (unsigned)n || (unsigned)d >= (unsigned)n) return;
    int pos = atomicAdd(&g_cur[d], 1);
    g_col[pos] = s;
    g_val[pos] = g_dinv[s] * ew[e] * g_dinv[d];
}

// ---------------- WMMA GEMM: g_hh(fp16) = X(fp16) @ W(fp16), fp32 accum ----------------
// 256 threads = 8 warps. BM=32 rows/block. W (128 x FOUT) staged fully in smem.
// Warp grid 2(M) x 4(N); per warp: NTW = FOUT/64 N-tiles of 16x16.
template <int FOUT>
__global__ void gemm_wmma_kernel(const __half* __restrict__ X,
                                 const __half* __restrict__ Wh, int n) {
    constexpr int BM = 32;
    constexpr int XLD = 136;              // halves per Xs row (mult of 8)
    constexpr int NTW = FOUT / 64;        // 2 (F=128) or 1 (F=64)
    constexpr int OLD = FOUT + 4;         // float out-staging ldm (mult of 4)
    __shared__ __align__(16) __half smh[BM * XLD + KDIM * FOUT];
    __half (*Xs)[XLD] = reinterpret_cast<__half (*)[XLD]>(smh);
    __half* Ws = smh + BM * XLD;
    float* outbuf = reinterpret_cast<float*>(smh);   // reused after compute

    const int t = threadIdx.x;
    const int w = t >> 5;
    const int rowBase = blockIdx.x * BM;
    const int mi = w >> 2;                // 0..1
    const int nj0 = (w & 3) * (16 * NTW); // N start col for this warp

    // stage W (KDIM x FOUT halves) : KDIM*FOUT/8 uint4
    for (int i = t; i < KDIM * FOUT / 8; i += 256)
        ((uint4*)Ws)[i] = ((const uint4*)Wh)[i];
    // stage X tile (BM x 128 halves): BM*16 uint4
    for (int i = t; i < BM * 16; i += 256) {
        int row = i >> 4, q = i & 15;
        uint4 v = make_uint4(0, 0, 0, 0);
        int grow = rowBase + row;
        if (grow < n) v = ((const uint4*)(X + (size_t)grow * KDIM))[q];
        *(uint4*)&Xs[row][q * 8] = v;
    }
    __syncthreads();

    wmma::fragment<wmma::accumulator, 16, 16, 16, float> acc[NTW];
    #pragma unroll
    for (int j = 0; j < NTW; j++) wmma::fill_fragment(acc[j], 0.0f);

    #pragma unroll
    for (int k = 0; k < KDIM; k += 16) {
        wmma::fragment<wmma::matrix_a, 16, 16, 16, __half, wmma::row_major> af;
        wmma::load_matrix_sync(af, &Xs[mi * 16][k], XLD);
        #pragma unroll
        for (int j = 0; j < NTW; j++) {
            wmma::fragment<wmma::matrix_b, 16, 16, 16, __half, wmma::row_major> bf;
            wmma::load_matrix_sync(bf, Ws + k * FOUT + nj0 + j * 16, FOUT);
            wmma::mma_sync(acc[j], af, bf, acc[j]);
        }
    }

    __syncthreads();   // done reading Xs/Ws; reuse as float staging
    #pragma unroll
    for (int j = 0; j < NTW; j++)
        wmma::store_matrix_sync(outbuf + (mi * 16) * OLD + nj0 + j * 16,
                                acc[j], OLD, wmma::mem_row_major);
    __syncthreads();

    // convert + coalesced fp16 store: BM*FOUT/8 chunks of 8 halves
    for (int i = t; i < BM * FOUT / 8; i += 256) {
        int row = i / (FOUT / 8), c = i % (FOUT / 8);
        int grow = rowBase + row;
        if (grow >= n) continue;
        const float* src = outbuf + row * OLD + c * 8;
        half2x4 hv;
        hv.a = __floats2half2_rn(src[0], src[1]);
        hv.b = __floats2half2_rn(src[2], src[3]);
        hv.c = __floats2half2_rn(src[4], src[5]);
        hv.d = __floats2half2_rn(src[6], src[7]);
        *(half2x4*)(g_hh + (size_t)grow * FOUT + c * 8) = hv;
    }
}

// ------- fused aggregate + bias + relu (F=128), warp per node; fp16 in/out -------
__global__ void agg_relu_kernel(const float* __restrict__ b, int n) {
    int w = (blockIdx.x * blockDim.x + threadIdx.x) >> 5;
    int lane = threadIdx.x & 31;
    if (w >= n) return;

    float di = g_dinv[w];
    float sv = di * di;
    half2x2 hq = *(const half2x2*)(g_hh + (size_t)w * 128 + lane * 4);
    float2 h0 = __half22float2(hq.a), h1 = __half22float2(hq.b);
    float4 acc = make_float4(h0.x * sv, h0.y * sv, h1.x * sv, h1.y * sv);

    int j = g_rowptr[w], end = g_rowptr[w + 1];
    for (; j + 4 <= end; j += 4) {
        int c0 = g_col[j], c1 = g_col[j + 1], c2 = g_col[j + 2], c3 = g_col[j + 3];
        float v0 = g_val[j], v1 = g_val[j + 1], v2 = g_val[j + 2], v3 = g_val[j + 3];
        half2x2 q0 = *(const half2x2*)(g_hh + (size_t)c0 * 128 + lane * 4);
        half2x2 q1 = *(const half2x2*)(g_hh + (size_t)c1 * 128 + lane * 4);
        half2x2 q2 = *(const half2x2*)(g_hh + (size_t)c2 * 128 + lane * 4);
        half2x2 q3 = *(const half2x2*)(g_hh + (size_t)c3 * 128 + lane * 4);
        float2 a0 = __half22float2(q0.a), b0 = __half22float2(q0.b);
        float2 a1 = __half22float2(q1.a), b1v = __half22float2(q1.b);
        float2 a2 = __half22float2(q2.a), b2v = __half22float2(q2.b);
        float2 a3 = __half22float2(q3.a), b3v = __half22float2(q3.b);
        acc.x += v0 * a0.x + v1 * a1.x + v2 * a2.x + v3 * a3.x;
        acc.y += v0 * a0.y + v1 * a1.y + v2 * a2.y + v3 * a3.y;
        acc.z += v0 * b0.x + v1 * b1v.x + v2 * b2v.x + v3 * b3v.x;
        acc.w += v0 * b0.y + v1 * b1v.y + v2 * b2v.y + v3 * b3v.y;
    }
    for (; j < end; j++) {
        int c0 = g_col[j];
        float v0 = g_val[j];
        half2x2 q0 = *(const half2x2*)(g_hh + (size_t)c0 * 128 + lane * 4);
        float2 a0 = __half22float2(q0.a), b0 = __half22float2(q0.b);
        acc.x += v0 * a0.x; acc.y += v0 * a0.y;
        acc.z += v0 * b0.x; acc.w += v0 * b0.y;
    }

    float4 bb = *(const float4*)(b + lane * 4);
    half2x2 ho;
    ho.a = __floats2half2_rn(fmaxf(acc.x + bb.x, 0.f), fmaxf(acc.y + bb.y, 0.f));
    ho.b = __floats2half2_rn(fmaxf(acc.z + bb.z, 0.f), fmaxf(acc.w + bb.w, 0.f));
    *(half2x2*)(g_act + (size_t)w * 128 + lane * 4) = ho;
}

// ------- fused aggregate + bias + log_softmax (F=64), warp per node -------
__global__ void agg_lsm_kernel(const float* __restrict__ b,
                               float* __restrict__ out, int n) {
    int w = (blockIdx.x * blockDim.x + threadIdx.x) >> 5;
    int lane = threadIdx.x & 31;
    if (w >= n) return;

    float di = g_dinv[w];
    float sv = di * di;
    __half2 hq = *(const __half2*)(g_hh + (size_t)w * 64 + lane * 2);
    float2 hs = __half22float2(hq);
    float2 acc = make_float2(hs.x * sv, hs.y * sv);

    int j = g_rowptr[w], end = g_rowptr[w + 1];
    for (; j + 4 <= end; j += 4) {
        int c0 = g_col[j], c1 = g_col[j + 1], c2 = g_col[j + 2], c3 = g_col[j + 3];
        float v0 = g_val[j], v1 = g_val[j + 1], v2 = g_val[j + 2], v3 = g_val[j + 3];
        __half2 u0 = *(const __half2*)(g_hh + (size_t)c0 * 64 + lane * 2);
        __half2 u1 = *(const __half2*)(g_hh + (size_t)c1 * 64 + lane * 2);
        __half2 u2 = *(const __half2*)(g_hh + (size_t)c2 * 64 + lane * 2);
        __half2 u3 = *(const __half2*)(g_hh + (size_t)c3 * 64 + lane * 2);
        float2 x0 = __half22float2(u0);
        float2 x1 = __half22float2(u1);
        float2 x2 = __half22float2(u2);
        float2 x3 = __half22float2(u3);
        acc.x += v0 * x0.x + v1 * x1.x + v2 * x2.x + v3 * x3.x;
        acc.y += v0 * x0.y + v1 * x1.y + v2 * x2.y + v3 * x3.y;
    }
    for (; j < end; j++) {
        int c0 = g_col[j];
        float v0 = g_val[j];
        __half2 u0 = *(const __half2*)(g_hh + (size_t)c0 * 64 + lane * 2);
        float2 x0 = __half22float2(u0);
        acc.x += v0 * x0.x; acc.y += v0 * x0.y;
    }

    float v0 = acc.x + b[lane * 2];
    float v1 = acc.y + b[lane * 2 + 1];

    float m = fmaxf(v0, v1);
    #pragma unroll
    for (int o = 16; o > 0; o >>= 1)
        m = fmaxf(m, __shfl_xor_sync(0xffffffffu, m, o));
    float s = expf(v0 - m) + expf(v1 - m);
    #pragma unroll
    for (int o = 16; o > 0; o >>= 1)
        s += __shfl_xor_sync(0xffffffffu, s, o);
    float lse = m + logf(s);

    *(float2*)(out + (size_t)w * 64 + lane * 2) = make_float2(v0 - lse, v1 - lse);
}

// ---------------- launch ----------------
static inline int cdiv(int a, int b) { return (a + b - 1) / b; }

extern "C" void kernel_launch(void* const* d_in, const int* in_sizes, int n_in,
                              void* d_out, int out_size) {
    const float* x = (const float*)d_in[0];
    const int* ei = (const int*)d_in[1];      // int32 edge_index [2, E]
    const float* ew = (const float*)d_in[2];
    const float* W1 = (const float*)d_in[3];
    const float* b1 = (const float*)d_in[4];
    const float* W2 = (const float*)d_in[5];
    const float* b2 = (const float*)d_in[6];
    const float* W3 = (const float*)d_in[7];
    const float* b3 = (const float*)d_in[8];
    float* outp = (float*)d_out;

    const int n = in_sizes[0] / 128;
    const int E = in_sizes[2];
    const int* srcI = ei;
    const int* dstI = ei + E;
    const int nblk = cdiv(n, SCAN_ITEMS);

    __half* xh;  cudaGetSymbolAddress((void**)&xh,  g_xh);
    __half* w1h; cudaGetSymbolAddress((void**)&w1h, g_w1h);
    __half* w2h; cudaGetSymbolAddress((void**)&w2h, g_w2h);
    __half* w3h; cudaGetSymbolAddress((void**)&w3h, g_w3h);
    __half* acth; cudaGetSymbolAddress((void**)&acth, g_act);

    // ---- fp16 conversions ----
    f2h_kernel<<<cdiv(n * 64, 256), 256>>>(x, xh, n * 64);
    f2h_kernel<<<cdiv(KDIM * 64, 256), 256>>>(W1, w1h, KDIM * 64);
    f2h_kernel<<<cdiv(KDIM * 64, 256), 256>>>(W2, w2h, KDIM * 64);
    f2h_kernel<<<cdiv(KDIM * 32, 256), 256>>>(W3, w3h, KDIM * 32);

    // ---- gcn_norm + CSR build ----
    deg_init_kernel<<<cdiv(n, 256), 256>>>(n);
    deg_acc_kernel<<<cdiv(E, 256), 256>>>(dstI, ew, E, n);
    dinv_kernel<<<cdiv(n, 256), 256>>>(n);
    scan_partial_kernel<<<nblk, 256>>>(n);
    scan_blocks_kernel<<<1, 128>>>(nblk, n);
    scan_final_kernel<<<nblk, 256>>>(n);
    scatter_kernel<<<cdiv(E, 256), 256>>>(srcI, dstI, ew, E, n);

    // ---- layer 1: 128 -> 128, relu ----
    gemm_wmma_kernel<128><<<cdiv(n, 32), 256>>>(xh, w1h, n);
    agg_relu_kernel<<<cdiv(n * 32, 256), 256>>>(b1, n);

    // ---- layer 2: 128 -> 128, relu ----
    gemm_wmma_kernel<128><<<cdiv(n, 32), 256>>>(acth, w2h, n);
    agg_relu_kernel<<<cdiv(n * 32, 256), 256>>>(b2, n);

    // ---- layer 3: 128 -> 64, log_softmax ----
    gemm_wmma_kernel<64><<<cdiv(n, 32), 256>>>(acth, w3h, n);
    agg_lsm_kernel<<<cdiv(n * 32, 256), 256>>>(b3, outp, n);
}

// round 16
// speedup vs baseline: 1.0261x; 1.0261x over previous
#include <cuda_runtime.h>
#include <cuda_fp16.h>
#include <mma.h>
#include <cstdint>

using namespace nvcuda;

#define NMAX 100000
#define EMAX 1600000
#define KDIM 128
#define SCAN_ITEMS 1024
#define SCAN_NBLK ((NMAX + SCAN_ITEMS - 1) / SCAN_ITEMS)

// -------- scratch (no allocations allowed; referenced directly from kernels) --------
__device__ __align__(16) float  g_deg[NMAX];
__device__ __align__(16) float  g_dinv[NMAX];
__device__ __align__(16) int    g_cnt[NMAX];
__device__ __align__(16) int    g_cur[NMAX];
__device__ __align__(16) int    g_rowptr[NMAX + 1];
__device__ __align__(16) int    g_bsum[SCAN_NBLK];
__device__ __align__(16) int    g_boff[SCAN_NBLK + 1];
__device__ __align__(16) int    g_col[EMAX];
__device__ __align__(16) float  g_val[EMAX];
__device__ __align__(16) __half g_hh[(size_t)NMAX * 128];   // fp16 hidden (GEMM out, agg in)
__device__ __align__(16) __half g_act[(size_t)NMAX * 128];  // fp16 activations (agg out, GEMM in)
__device__ __align__(16) __half g_xh[(size_t)NMAX * 128];   // fp16 copy of input x
__device__ __align__(16) __half g_w1h[KDIM * 128];
__device__ __align__(16) __half g_w2h[KDIM * 128];
__device__ __align__(16) __half g_w3h[KDIM * 64];

struct __align__(8)  half2x2 { __half2 a, b; };
struct __align__(16) half2x4 { __half2 a, b, c, d; };

// ---------------- fp32 -> fp16 conversion (half2 granularity) ----------------
__global__ void f2h_kernel(const float* __restrict__ in, __half* __restrict__ out, int n2) {
    int i = blockIdx.x * blockDim.x + threadIdx.x;
    if (i < n2) {
        float2 v = ((const float2*)in)[i];
        ((__half2*)out)[i] = __floats2half2_rn(v.x, v.y);
    }
}

// ---------------- degree / histogram init ----------------
__global__ void deg_init_kernel(int n) {
    int i = blockIdx.x * blockDim.x + threadIdx.x;
    if (i < n) { g_deg[i] = 1.0f; g_cnt[i] = 0; }  // self-loop weight 1
}

__global__ void deg_acc_kernel(const int* __restrict__ dst,
                               const float* __restrict__ ew, int E, int n) {
    int e = blockIdx.x * blockDim.x + threadIdx.x;
    if (e < E) {
        int d = dst[e];
        if ((unsigned)d < (unsigned)n) {
            atomicAdd(&g_deg[d], ew[e]);
            atomicAdd(&g_cnt[d], 1);
        }
    }
}

__global__ void dinv_kernel(int n) {
    int i = blockIdx.x * blockDim.x + threadIdx.x;
    if (i < n) {
        float d = g_deg[i];
        g_dinv[i] = d > 0.f ? rsqrtf(d) : 0.f;
    }
}

// ---------------- 3-phase grid-wide exclusive scan: cnt -> rowptr, cur ----------------
__global__ void scan_partial_kernel(int n) {
    __shared__ int sm[256];
    int t = threadIdx.x;
    int base = blockIdx.x * SCAN_ITEMS;
    int s = 0;
    #pragma unroll
    for (int i = 0; i < SCAN_ITEMS / 256; i++) {
        int idx = base + i * 256 + t;
        if (idx < n) s += g_cnt[idx];
    }
    sm[t] = s;
    __syncthreads();
    #pragma unroll
    for (int off = 128; off > 0; off >>= 1) {
        if (t < off) sm[t] += sm[t + off];
        __syncthreads();
    }
    if (t == 0) g_bsum[blockIdx.x] = sm[0];
}

__global__ void scan_blocks_kernel(int nblk, int n) {
    __shared__ int sm[128];
    int t = threadIdx.x;
    sm[t] = (t < nblk) ? g_bsum[t] : 0;
    __syncthreads();
    for (int off = 1; off < 128; off <<= 1) {
        int v = (t >= off) ? sm[t - off] : 0;
        __syncthreads();
        sm[t] += v;
        __syncthreads();
    }
    if (t < nblk) g_boff[t] = (t == 0) ? 0 : sm[t - 1];
    if (t == nblk - 1) {
        g_boff[nblk] = sm[t];
        g_rowptr[n] = sm[t];
    }
}

__global__ void scan_final_kernel(int n) {
    constexpr int IPT = SCAN_ITEMS / 256;
    __shared__ int sm[256];
    int t = threadIdx.x;
    int base = blockIdx.x * SCAN_ITEMS + t * IPT;

    int v[IPT];
    int s = 0;
    #pragma unroll
    for (int i = 0; i < IPT; i++) {
        int idx = base + i;
        v[i] = (idx < n) ? g_cnt[idx] : 0;
        s += v[i];
    }
    sm[t] = s;
    __syncthreads();
    for (int off = 1; off < 256; off <<= 1) {
        int u = (t >= off) ? sm[t - off] : 0;
        __syncthreads();
        sm[t] += u;
        __syncthreads();
    }
    int run = g_boff[blockIdx.x] + ((t == 0) ? 0 : sm[t - 1]);
    #pragma unroll
    for (int i = 0; i < IPT; i++) {
        int idx = base + i;
        if (idx < n) {
            g_rowptr[idx] = run;
            g_cur[idx] = run;
            run += v[i];
        }
    }
}

// ---------------- scatter edges into CSR (col + precomputed norm) ----------------
__global__ void scatter_kernel(const int* __restrict__ src,
                               const int* __restrict__ dst,
                               const float* __restrict__ ew, int E, int n) {
    int e = blockIdx.x * blockDim.x + threadIdx.x;
    if (e >= E) return;
    int s = src[e];
    int d = dst[e];
    if ((unsigned)s >= (unsigned)n || (unsigned)d >= (unsigned)n) return;
    int pos = atomicAdd(&g_cur[d], 1);
    g_col[pos] = s;
    g_val[pos] = g_dinv[s] * ew[e] * g_dinv[d];
}

// ---------------- WMMA GEMM: g_hh(fp16) = X(fp16) @ W(fp16), fp32 accum ----------------
// BM=128 rows/block (782 blocks), K split into 2 chunks of 64 to fit 48KB static smem.
// 8 warps, warp w owns M-tile w (16 rows) x ALL N-tiles (NT = FOUT/16).
template <int FOUT>
__global__ void gemm_wmma_kernel(const __half* __restrict__ X,
                                 const __half* __restrict__ Wh, int n) {
    constexpr int BM = 128;
    constexpr int BKC = 64;               // K-chunk
    constexpr int XLD = BKC + 8;          // 72 halves per Xs row
    constexpr int NT = FOUT / 16;         // 8 or 4
    constexpr int OLD = FOUT + 4;         // fp32 staging ldm
    __shared__ __align__(16) __half smh[BM * XLD + BKC * FOUT];  // 34816B (F=128)
    __half (*Xs)[XLD] = reinterpret_cast<__half (*)[XLD]>(smh);
    __half* Ws = smh + BM * XLD;
    float* outbuf = reinterpret_cast<float*>(smh);   // reused in epilogue

    const int t = threadIdx.x;
    const int w = t >> 5;
    const int rowBase = blockIdx.x * BM;

    wmma::fragment<wmma::accumulator, 16, 16, 16, float> acc[NT];
    #pragma unroll
    for (int j = 0; j < NT; j++) wmma::fill_fragment(acc[j], 0.0f);

    #pragma unroll
    for (int kc = 0; kc < KDIM; kc += BKC) {
        // stage X chunk: BM rows x BKC halves = BM*BKC/8 uint4 = 1024 -> 4/thread
        #pragma unroll
        for (int i = 0; i < BM * BKC / 8 / 256; i++) {
            int idx = i * 256 + t;
            int row = idx >> 3, q = idx & 7;
            uint4 v = make_uint4(0, 0, 0, 0);
            int grow = rowBase + row;
            if (grow < n) v = *(const uint4*)(X + (size_t)grow * KDIM + kc + q * 8);
            *(uint4*)&Xs[row][q * 8] = v;
        }
        // stage W chunk: BKC x FOUT halves = BKC*FOUT/8 uint4
        #pragma unroll
        for (int i = 0; i < BKC * FOUT / 8 / 256; i++) {
            int idx = i * 256 + t;
            int kk = idx / (FOUT / 8), c = idx % (FOUT / 8);
            ((uint4*)Ws)[idx] = *(const uint4*)(Wh + (size_t)(kc + kk) * FOUT + c * 8);
        }
        __syncthreads();

        #pragma unroll
        for (int k = 0; k < BKC; k += 16) {
            wmma::fragment<wmma::matrix_a, 16, 16, 16, __half, wmma::row_major> af;
            wmma::load_matrix_sync(af, &Xs[w * 16][k], XLD);
            #pragma unroll
            for (int j = 0; j < NT; j++) {
                wmma::fragment<wmma::matrix_b, 16, 16, 16, __half, wmma::row_major> bf;
                wmma::load_matrix_sync(bf, Ws + k * FOUT + j * 16, FOUT);
                wmma::mma_sync(acc[j], af, bf, acc[j]);
            }
        }
        __syncthreads();
    }

    // epilogue: two 64-row halves through fp32 smem staging
    #pragma unroll
    for (int h = 0; h < 2; h++) {
        if ((w >> 2) == h) {
            #pragma unroll
            for (int j = 0; j < NT; j++)
                wmma::store_matrix_sync(outbuf + (w * 16 - h * 64) * OLD + j * 16,
                                        acc[j], OLD, wmma::mem_row_major);
        }
        __syncthreads();
        for (int i = t; i < 64 * FOUT / 8; i += 256) {
            int row = i / (FOUT / 8), c = i % (FOUT / 8);
            int grow = rowBase + h * 64 + row;
            if (grow < n) {
                const float* src = outbuf + row * OLD + c * 8;
                half2x4 hv;
                hv.a = __floats2half2_rn(src[0], src[1]);
                hv.b = __floats2half2_rn(src[2], src[3]);
                hv.c = __floats2half2_rn(src[4], src[5]);
                hv.d = __floats2half2_rn(src[6], src[7]);
                *(half2x4*)(g_hh + (size_t)grow * FOUT + c * 8) = hv;
            }
        }
        __syncthreads();
    }
}

// ------- fused aggregate + bias + relu (F=128), warp per node; fp16 in/out -------
__global__ void agg_relu_kernel(const float* __restrict__ b, int n) {
    int w = (blockIdx.x * blockDim.x + threadIdx.x) >> 5;
    int lane = threadIdx.x & 31;
    if (w >= n) return;

    float di = g_dinv[w];
    float sv = di * di;
    half2x2 hq = *(const half2x2*)(g_hh + (size_t)w * 128 + lane * 4);
    float2 h0 = __half22float2(hq.a), h1 = __half22float2(hq.b);
    float4 acc = make_float4(h0.x * sv, h0.y * sv, h1.x * sv, h1.y * sv);

    int j = g_rowptr[w], end = g_rowptr[w + 1];
    for (; j + 4 <= end; j += 4) {
        int c0 = g_col[j], c1 = g_col[j + 1], c2 = g_col[j + 2], c3 = g_col[j + 3];
        float v0 = g_val[j], v1 = g_val[j + 1], v2 = g_val[j + 2], v3 = g_val[j + 3];
        half2x2 q0 = *(const half2x2*)(g_hh + (size_t)c0 * 128 + lane * 4);
        half2x2 q1 = *(const half2x2*)(g_hh + (size_t)c1 * 128 + lane * 4);
        half2x2 q2 = *(const half2x2*)(g_hh + (size_t)c2 * 128 + lane * 4);
        half2x2 q3 = *(const half2x2*)(g_hh + (size_t)c3 * 128 + lane * 4);
        float2 a0 = __half22float2(q0.a), b0 = __half22float2(q0.b);
        float2 a1 = __half22float2(q1.a), b1v = __half22float2(q1.b);
        float2 a2 = __half22float2(q2.a), b2v = __half22float2(q2.b);
        float2 a3 = __half22float2(q3.a), b3v = __half22float2(q3.b);
        acc.x += v0 * a0.x + v1 * a1.x + v2 * a2.x + v3 * a3.x;
        acc.y += v0 * a0.y + v1 * a1.y + v2 * a2.y + v3 * a3.y;
        acc.z += v0 * b0.x + v1 * b1v.x + v2 * b2v.x + v3 * b3v.x;
        acc.w += v0 * b0.y + v1 * b1v.y + v2 * b2v.y + v3 * b3v.y;
    }
    for (; j < end; j++) {
        int c0 = g_col[j];
        float v0 = g_val[j];
        half2x2 q0 = *(const half2x2*)(g_hh + (size_t)c0 * 128 + lane * 4);
        float2 a0 = __half22float2(q0.a), b0 = __half22float2(q0.b);
        acc.x += v0 * a0.x; acc.y += v0 * a0.y;
        acc.z += v0 * b0.x; acc.w += v0 * b0.y;
    }

    float4 bb = *(const float4*)(b + lane * 4);
    half2x2 ho;
    ho.a = __floats2half2_rn(fmaxf(acc.x + bb.x, 0.f), fmaxf(acc.y + bb.y, 0.f));
    ho.b = __floats2half2_rn(fmaxf(acc.z + bb.z, 0.f), fmaxf(acc.w + bb.w, 0.f));
    *(half2x2*)(g_act + (size_t)w * 128 + lane * 4) = ho;
}

// ------- fused aggregate + bias + log_softmax (F=64), warp per node -------
__global__ void agg_lsm_kernel(const float* __restrict__ b,
                               float* __restrict__ out, int n) {
    int w = (blockIdx.x * blockDim.x + threadIdx.x) >> 5;
    int lane = threadIdx.x & 31;
    if (w >= n) return;

    float di = g_dinv[w];
    float sv = di * di;
    __half2 hq = *(const __half2*)(g_hh + (size_t)w * 64 + lane * 2);
    float2 hs = __half22float2(hq);
    float2 acc = make_float2(hs.x * sv, hs.y * sv);

    int j = g_rowptr[w], end = g_rowptr[w + 1];
    for (; j + 4 <= end; j += 4) {
        int c0 = g_col[j], c1 = g_col[j + 1], c2 = g_col[j + 2], c3 = g_col[j + 3];
        float v0 = g_val[j], v1 = g_val[j + 1], v2 = g_val[j + 2], v3 = g_val[j + 3];
        __half2 u0 = *(const __half2*)(g_hh + (size_t)c0 * 64 + lane * 2);
        __half2 u1 = *(const __half2*)(g_hh + (size_t)c1 * 64 + lane * 2);
        __half2 u2 = *(const __half2*)(g_hh + (size_t)c2 * 64 + lane * 2);
        __half2 u3 = *(const __half2*)(g_hh + (size_t)c3 * 64 + lane * 2);
        float2 x0 = __half22float2(u0);
        float2 x1 = __half22float2(u1);
        float2 x2 = __half22float2(u2);
        float2 x3 = __half22float2(u3);
        acc.x += v0 * x0.x + v1 * x1.x + v2 * x2.x + v3 * x3.x;
        acc.y += v0 * x0.y + v1 * x1.y + v2 * x2.y + v3 * x3.y;
    }
    for (; j < end; j++) {
        int c0 = g_col[j];
        float v0 = g_val[j];
        __half2 u0 = *(const __half2*)(g_hh + (size_t)c0 * 64 + lane * 2);
        float2 x0 = __half22float2(u0);
        acc.x += v0 * x0.x; acc.y += v0 * x0.y;
    }

    float v0 = acc.x + b[lane * 2];
    float v1 = acc.y + b[lane * 2 + 1];

    float m = fmaxf(v0, v1);
    #pragma unroll
    for (int o = 16; o > 0; o >>= 1)
        m = fmaxf(m, __shfl_xor_sync(0xffffffffu, m, o));
    float s = expf(v0 - m) + expf(v1 - m);
    #pragma unroll
    for (int o = 16; o > 0; o >>= 1)
        s += __shfl_xor_sync(0xffffffffu, s, o);
    float lse = m + logf(s);

    *(float2*)(out + (size_t)w * 64 + lane * 2) = make_float2(v0 - lse, v1 - lse);
}

// ---------------- launch ----------------
static inline int cdiv(int a, int b) { return (a + b - 1) / b; }

extern "C" void kernel_launch(void* const* d_in, const int* in_sizes, int n_in,
                              void* d_out, int out_size) {
    const float* x = (const float*)d_in[0];
    const int* ei = (const int*)d_in[1];      // int32 edge_index [2, E]
    const float* ew = (const float*)d_in[2];
    const float* W1 = (const float*)d_in[3];
    const float* b1 = (const float*)d_in[4];
    const float* W2 = (const float*)d_in[5];
    const float* b2 = (const float*)d_in[6];
    const float* W3 = (const float*)d_in[7];
    const float* b3 = (const float*)d_in[8];
    float* outp = (float*)d_out;

    const int n = in_sizes[0] / 128;
    const int E = in_sizes[2];
    const int* srcI = ei;
    const int* dstI = ei + E;
    const int nblk = cdiv(n, SCAN_ITEMS);

    __half* xh;  cudaGetSymbolAddress((void**)&xh,  g_xh);
    __half* w1h; cudaGetSymbolAddress((void**)&w1h, g_w1h);
    __half* w2h; cudaGetSymbolAddress((void**)&w2h, g_w2h);
    __half* w3h; cudaGetSymbolAddress((void**)&w3h, g_w3h);
    __half* acth; cudaGetSymbolAddress((void**)&acth, g_act);

    // ---- fp16 conversions ----
    f2h_kernel<<<cdiv(n * 64, 256), 256>>>(x, xh, n * 64);
    f2h_kernel<<<cdiv(KDIM * 64, 256), 256>>>(W1, w1h, KDIM * 64);
    f2h_kernel<<<cdiv(KDIM * 64, 256), 256>>>(W2, w2h, KDIM * 64);
    f2h_kernel<<<cdiv(KDIM * 32, 256), 256>>>(W3, w3h, KDIM * 32);

    // ---- gcn_norm + CSR build ----
    deg_init_kernel<<<cdiv(n, 256), 256>>>(n);
    deg_acc_kernel<<<cdiv(E, 256), 256>>>(dstI, ew, E, n);
    dinv_kernel<<<cdiv(n, 256), 256>>>(n);
    scan_partial_kernel<<<nblk, 256>>>(n);
    scan_blocks_kernel<<<1, 128>>>(nblk, n);
    scan_final_kernel<<<nblk, 256>>>(n);
    scatter_kernel<<<cdiv(E, 256), 256>>>(srcI, dstI, ew, E, n);

    // ---- layer 1: 128 -> 128, relu ----
    gemm_wmma_kernel<128><<<cdiv(n, 128), 256>>>(xh, w1h, n);
    agg_relu_kernel<<<cdiv(n * 32, 256), 256>>>(b1, n);

    // ---- layer 2: 128 -> 128, relu ----
    gemm_wmma_kernel<128><<<cdiv(n, 128), 256>>>(acth, w2h, n);
    agg_relu_kernel<<<cdiv(n * 32, 256), 256>>>(b2, n);

    // ---- layer 3: 128 -> 64, log_softmax ----
    gemm_wmma_kernel<64><<<cdiv(n, 128), 256>>>(acth, w3h, n);
    agg_lsm_kernel<<<cdiv(n * 32, 256), 256>>>(b3, outp, n);
}

// round 17
// speedup vs baseline: 1.0296x; 1.0035x over previous
#include <cuda_runtime.h>
#include <cuda_fp16.h>
#include <mma.h>
#include <cstdint>

using namespace nvcuda;

#define NMAX 100000
#define EMAX 1600000
#define KDIM 128
#define SCAN_ITEMS 1024
#define SCAN_NBLK ((NMAX + SCAN_ITEMS - 1) / SCAN_ITEMS)

// -------- scratch (no allocations allowed; referenced directly from kernels) --------
__device__ __align__(16) float  g_deg[NMAX];
__device__ __align__(16) float  g_dinv[NMAX];
__device__ __align__(16) int    g_cnt[NMAX];
__device__ __align__(16) int    g_cur[NMAX];
__device__ __align__(16) int    g_rowptr[NMAX + 2];
__device__ __align__(16) int    g_bsum[SCAN_NBLK];
__device__ __align__(16) int    g_boff[SCAN_NBLK + 1];
__device__ __align__(16) int    g_col[EMAX];
__device__ __align__(16) float  g_val[EMAX];
__device__ __align__(16) __half g_hh[(size_t)NMAX * 128];   // fp16 hidden (GEMM out, agg in)
__device__ __align__(16) __half g_act[(size_t)NMAX * 128];  // fp16 activations (agg out, GEMM in)
__device__ __align__(16) __half g_xh[(size_t)NMAX * 128];   // fp16 copy of input x
__device__ __align__(16) __half g_w1h[KDIM * 128];
__device__ __align__(16) __half g_w2h[KDIM * 128];
__device__ __align__(16) __half g_w3h[KDIM * 64];

struct __align__(8)  half2x2 { __half2 a, b; };
struct __align__(16) half2x4 { __half2 a, b, c, d; };

// ---------------- fp32 -> fp16 conversion (half2 granularity) ----------------
__global__ void f2h_kernel(const float* __restrict__ in, __half* __restrict__ out, int n2) {
    int i = blockIdx.x * blockDim.x + threadIdx.x;
    if (i < n2) {
        float2 v = ((const float2*)in)[i];
        ((__half2*)out)[i] = __floats2half2_rn(v.x, v.y);
    }
}

// ---------------- degree / histogram init ----------------
__global__ void deg_init_kernel(int n) {
    int i = blockIdx.x * blockDim.x + threadIdx.x;
    if (i < n) { g_deg[i] = 1.0f; g_cnt[i] = 0; }  // self-loop weight 1
}

__global__ void deg_acc_kernel(const int* __restrict__ dst,
                               const float* __restrict__ ew, int E, int n) {
    int e = blockIdx.x * blockDim.x + threadIdx.x;
    if (e < E) {
        int d = dst[e];
        if ((unsigned)d < (unsigned)n) {
            atomicAdd(&g_deg[d], ew[e]);
            atomicAdd(&g_cnt[d], 1);
        }
    }
}

__global__ void dinv_kernel(int n) {
    int i = blockIdx.x * blockDim.x + threadIdx.x;
    if (i < n) {
        float d = g_deg[i];
        g_dinv[i] = d > 0.f ? rsqrtf(d) : 0.f;
    }
}

// ---------------- 3-phase grid-wide exclusive scan: cnt -> rowptr, cur ----------------
__global__ void scan_partial_kernel(int n) {
    __shared__ int sm[256];
    int t = threadIdx.x;
    int base = blockIdx.x * SCAN_ITEMS;
    int s = 0;
    #pragma unroll
    for (int i = 0; i < SCAN_ITEMS / 256; i++) {
        int idx = base + i * 256 + t;
        if (idx < n) s += g_cnt[idx];
    }
    sm[t] = s;
    __syncthreads();
    #pragma unroll
    for (int off = 128; off > 0; off >>= 1) {
        if (t < off) sm[t] += sm[t + off];
        __syncthreads();
    }
    if (t == 0) g_bsum[blockIdx.x] = sm[0];
}

__global__ void scan_blocks_kernel(int nblk, int n) {
    __shared__ int sm[128];
    int t = threadIdx.x;
    sm[t] = (t < nblk) ? g_bsum[t] : 0;
    __syncthreads();
    for (int off = 1; off < 128; off <<= 1) {
        int v = (t >= off) ? sm[t - off] : 0;
        __syncthreads();
        sm[t] += v;
        __syncthreads();
    }
    if (t < nblk) g_boff[t] = (t == 0) ? 0 : sm[t - 1];
    if (t == nblk - 1) {
        g_boff[nblk] = sm[t];
        g_rowptr[n] = sm[t];
        g_rowptr[n + 1] = sm[t];   // pad so node n (inactive half) reads end==start
    }
}

__global__ void scan_final_kernel(int n) {
    constexpr int IPT = SCAN_ITEMS / 256;
    __shared__ int sm[256];
    int t = threadIdx.x;
    int base = blockIdx.x * SCAN_ITEMS + t * IPT;

    int v[IPT];
    int s = 0;
    #pragma unroll
    for (int i = 0; i < IPT; i++) {
        int idx = base + i;
        v[i] = (idx < n) ? g_cnt[idx] : 0;
        s += v[i];
    }
    sm[t] = s;
    __syncthreads();
    for (int off = 1; off < 256; off <<= 1) {
        int u = (t >= off) ? sm[t - off] : 0;
        __syncthreads();
        sm[t] += u;
        __syncthreads();
    }
    int run = g_boff[blockIdx.x] + ((t == 0) ? 0 : sm[t - 1]);
    #pragma unroll
    for (int i = 0; i < IPT; i++) {
        int idx = base + i;
        if (idx < n) {
            g_rowptr[idx] = run;
            g_cur[idx] = run;
            run += v[i];
        }
    }
}

// ---------------- scatter edges into CSR (col + precomputed norm) ----------------
__global__ void scatter_kernel(const int* __restrict__ src,
                               const int* __restrict__ dst,
                               const float* __restrict__ ew, int E, int n) {
    int e = blockIdx.x * blockDim.x + threadIdx.x;
    if (e >= E) return;
    int s = src[e];
    int d = dst[e];
    if ((unsigned)s >= (unsigned)n || (unsigned)d >= (unsigned)n) return;
    int pos = atomicAdd(&g_cur[d], 1);
    g_col[pos] = s;
    g_val[pos] = g_dinv[s] * ew[e] * g_dinv[d];
}

// ---------------- WMMA GEMM: g_hh(fp16) = X(fp16) @ W(fp16), fp32 accum ----------------
template <int FOUT>
__global__ void gemm_wmma_kernel(const __half* __restrict__ X,
                                 const __half* __restrict__ Wh, int n) {
    constexpr int BM = 128;
    constexpr int BKC = 64;
    constexpr int XLD = BKC + 8;
    constexpr int NT = FOUT / 16;
    constexpr int OLD = FOUT + 4;
    __shared__ __align__(16) __half smh[BM * XLD + BKC * FOUT];
    __half (*Xs)[XLD] = reinterpret_cast<__half (*)[XLD]>(smh);
    __half* Ws = smh + BM * XLD;
    float* outbuf = reinterpret_cast<float*>(smh);

    const int t = threadIdx.x;
    const int w = t >> 5;
    const int rowBase = blockIdx.x * BM;

    wmma::fragment<wmma::accumulator, 16, 16, 16, float> acc[NT];
    #pragma unroll
    for (int j = 0; j < NT; j++) wmma::fill_fragment(acc[j], 0.0f);

    #pragma unroll
    for (int kc = 0; kc < KDIM; kc += BKC) {
        #pragma unroll
        for (int i = 0; i < BM * BKC / 8 / 256; i++) {
            int idx = i * 256 + t;
            int row = idx >> 3, q = idx & 7;
            uint4 v = make_uint4(0, 0, 0, 0);
            int grow = rowBase + row;
            if (grow < n) v = *(const uint4*)(X + (size_t)grow * KDIM + kc + q * 8);
            *(uint4*)&Xs[row][q * 8] = v;
        }
        #pragma unroll
        for (int i = 0; i < BKC * FOUT / 8 / 256; i++) {
            int idx = i * 256 + t;
            int kk = idx / (FOUT / 8), c = idx % (FOUT / 8);
            ((uint4*)Ws)[idx] = *(const uint4*)(Wh + (size_t)(kc + kk) * FOUT + c * 8);
        }
        __syncthreads();

        #pragma unroll
        for (int k = 0; k < BKC; k += 16) {
            wmma::fragment<wmma::matrix_a, 16, 16, 16, __half, wmma::row_major> af;
            wmma::load_matrix_sync(af, &Xs[w * 16][k], XLD);
            #pragma unroll
            for (int j = 0; j < NT; j++) {
                wmma::fragment<wmma::matrix_b, 16, 16, 16, __half, wmma::row_major> bf;
                wmma::load_matrix_sync(bf, Ws + k * FOUT + j * 16, FOUT);
                wmma::mma_sync(acc[j], af, bf, acc[j]);
            }
        }
        __syncthreads();
    }

    #pragma unroll
    for (int h = 0; h < 2; h++) {
        if ((w >> 2) == h) {
            #pragma unroll
            for (int j = 0; j < NT; j++)
                wmma::store_matrix_sync(outbuf + (w * 16 - h * 64) * OLD + j * 16,
                                        acc[j], OLD, wmma::mem_row_major);
        }
        __syncthreads();
        for (int i = t; i < 64 * FOUT / 8; i += 256) {
            int row = i / (FOUT / 8), c = i % (FOUT / 8);
            int grow = rowBase + h * 64 + row;
            if (grow < n) {
                const float* src = outbuf + row * OLD + c * 8;
                half2x4 hv;
                hv.a = __floats2half2_rn(src[0], src[1]);
                hv.b = __floats2half2_rn(src[2], src[3]);
                hv.c = __floats2half2_rn(src[4], src[5]);
                hv.d = __floats2half2_rn(src[6], src[7]);
                *(half2x4*)(g_hh + (size_t)grow * FOUT + c * 8) = hv;
            }
        }
        __syncthreads();
    }
}

// ------- fused aggregate + bias + relu (F=128): 2 nodes/warp, 16-lane halves -------
__global__ void agg_relu_kernel(const float* __restrict__ b, int n) {
    int gw = (blockIdx.x * blockDim.x + threadIdx.x) >> 5;
    int lane = threadIdx.x & 31;
    int hl = lane & 15;
    int node = gw * 2 + (lane >> 4);
    bool act = node < n;

    float di = act ? g_dinv[node] : 0.f;
    float sv = di * di;
    int safe = act ? node : 0;

    half2x4 hq = *(const half2x4*)(g_hh + (size_t)safe * 128 + hl * 8);
    float2 s0 = __half22float2(hq.a), s1 = __half22float2(hq.b);
    float2 s2 = __half22float2(hq.c), s3 = __half22float2(hq.d);
    float acc[8] = { s0.x * sv, s0.y * sv, s1.x * sv, s1.y * sv,
                     s2.x * sv, s2.y * sv, s3.x * sv, s3.y * sv };

    int j = act ? g_rowptr[node] : 0;
    int end = act ? g_rowptr[node + 1] : 0;

    while (__any_sync(0xffffffffu, j < end)) {
        bool p0 = j < end, p1 = j + 1 < end;
        int c0 = p0 ? g_col[j] : 0;
        int c1 = p1 ? g_col[j + 1] : 0;
        float v0 = p0 ? g_val[j] : 0.f;
        float v1 = p1 ? g_val[j + 1] : 0.f;
        half2x4 q0 = *(const half2x4*)(g_hh + (size_t)c0 * 128 + hl * 8);
        half2x4 q1 = *(const half2x4*)(g_hh + (size_t)c1 * 128 + hl * 8);
        float2 a0 = __half22float2(q0.a), a1 = __half22float2(q0.b);
        float2 a2 = __half22float2(q0.c), a3 = __half22float2(q0.d);
        float2 b0 = __half22float2(q1.a), b1 = __half22float2(q1.b);
        float2 b2 = __half22float2(q1.c), b3 = __half22float2(q1.d);
        acc[0] += v0 * a0.x + v1 * b0.x;
        acc[1] += v0 * a0.y + v1 * b0.y;
        acc[2] += v0 * a1.x + v1 * b1.x;
        acc[3] += v0 * a1.y + v1 * b1.y;
        acc[4] += v0 * a2.x + v1 * b2.x;
        acc[5] += v0 * a2.y + v1 * b2.y;
        acc[6] += v0 * a3.x + v1 * b3.x;
        acc[7] += v0 * a3.y + v1 * b3.y;
        j += 2;
    }

    if (act) {
        float4 bb0 = *(const float4*)(b + hl * 8);
        float4 bb1 = *(const float4*)(b + hl * 8 + 4);
        half2x4 ho;
        ho.a = __floats2half2_rn(fmaxf(acc[0] + bb0.x, 0.f), fmaxf(acc[1] + bb0.y, 0.f));
        ho.b = __floats2half2_rn(fmaxf(acc[2] + bb0.z, 0.f), fmaxf(acc[3] + bb0.w, 0.f));
        ho.c = __floats2half2_rn(fmaxf(acc[4] + bb1.x, 0.f), fmaxf(acc[5] + bb1.y, 0.f));
        ho.d = __floats2half2_rn(fmaxf(acc[6] + bb1.z, 0.f), fmaxf(acc[7] + bb1.w, 0.f));
        *(half2x4*)(g_act + (size_t)node * 128 + hl * 8) = ho;
    }
}

// ------- fused aggregate + bias + log_softmax (F=64): 2 nodes/warp -------
__global__ void agg_lsm_kernel(const float* __restrict__ b,
                               float* __restrict__ out, int n) {
    int gw = (blockIdx.x * blockDim.x + threadIdx.x) >> 5;
    int lane = threadIdx.x & 31;
    int hl = lane & 15;
    int node = gw * 2 + (lane >> 4);
    bool act = node < n;

    float di = act ? g_dinv[node] : 0.f;
    float sv = di * di;
    int safe = act ? node : 0;

    half2x2 hq = *(const half2x2*)(g_hh + (size_t)safe * 64 + hl * 4);
    float2 s0 = __half22float2(hq.a), s1 = __half22float2(hq.b);
    float acc[4] = { s0.x * sv, s0.y * sv, s1.x * sv, s1.y * sv };

    int j = act ? g_rowptr[node] : 0;
    int end = act ? g_rowptr[node + 1] : 0;

    while (__any_sync(0xffffffffu, j < end)) {
        bool p0 = j < end, p1 = j + 1 < end;
        int c0 = p0 ? g_col[j] : 0;
        int c1 = p1 ? g_col[j + 1] : 0;
        float v0 = p0 ? g_val[j] : 0.f;
        float v1 = p1 ? g_val[j + 1] : 0.f;
        half2x2 q0 = *(const half2x2*)(g_hh + (size_t)c0 * 64 + hl * 4);
        half2x2 q1 = *(const half2x2*)(g_hh + (size_t)c1 * 64 + hl * 4);
        float2 a0 = __half22float2(q0.a), a1 = __half22float2(q0.b);
        float2 b0 = __half22float2(q1.a), b1 = __half22float2(q1.b);
        acc[0] += v0 * a0.x + v1 * b0.x;
        acc[1] += v0 * a0.y + v1 * b0.y;
        acc[2] += v0 * a1.x + v1 * b1.x;
        acc[3] += v0 * a1.y + v1 * b1.y;
        j += 2;
    }

    float4 bb = *(const float4*)(b + hl * 4);
    float v0 = acc[0] + bb.x, v1 = acc[1] + bb.y;
    float v2 = acc[2] + bb.z, v3 = acc[3] + bb.w;

    float m = fmaxf(fmaxf(v0, v1), fmaxf(v2, v3));
    #pragma unroll
    for (int o = 8; o > 0; o >>= 1)
        m = fmaxf(m, __shfl_xor_sync(0xffffffffu, m, o, 16));
    float s = expf(v0 - m) + expf(v1 - m) + expf(v2 - m) + expf(v3 - m);
    #pragma unroll
    for (int o = 8; o > 0; o >>= 1)
        s += __shfl_xor_sync(0xffffffffu, s, o, 16);
    float lse = m + logf(s);

    if (act)
        *(float4*)(out + (size_t)node * 64 + hl * 4) =
            make_float4(v0 - lse, v1 - lse, v2 - lse, v3 - lse);
}

// ---------------- launch ----------------
static inline int cdiv(int a, int b) { return (a + b - 1) / b; }

extern "C" void kernel_launch(void* const* d_in, const int* in_sizes, int n_in,
                              void* d_out, int out_size) {
    const float* x = (const float*)d_in[0];
    const int* ei = (const int*)d_in[1];      // int32 edge_index [2, E]
    const float* ew = (const float*)d_in[2];
    const float* W1 = (const float*)d_in[3];
    const float* b1 = (const float*)d_in[4];
    const float* W2 = (const float*)d_in[5];
    const float* b2 = (const float*)d_in[6];
    const float* W3 = (const float*)d_in[7];
    const float* b3 = (const float*)d_in[8];
    float* outp = (float*)d_out;

    const int n = in_sizes[0] / 128;
    const int E = in_sizes[2];
    const int* srcI = ei;
    const int* dstI = ei + E;
    const int nblk = cdiv(n, SCAN_ITEMS);

    __half* xh;  cudaGetSymbolAddress((void**)&xh,  g_xh);
    __half* w1h; cudaGetSymbolAddress((void**)&w1h, g_w1h);
    __half* w2h; cudaGetSymbolAddress((void**)&w2h, g_w2h);
    __half* w3h; cudaGetSymbolAddress((void**)&w3h, g_w3h);
    __half* acth; cudaGetSymbolAddress((void**)&acth, g_act);

    // ---- fp16 conversions ----
    f2h_kernel<<<cdiv(n * 64, 256), 256>>>(x, xh, n * 64);
    f2h_kernel<<<cdiv(KDIM * 64, 256), 256>>>(W1, w1h, KDIM * 64);
    f2h_kernel<<<cdiv(KDIM * 64, 256), 256>>>(W2, w2h, KDIM * 64);
    f2h_kernel<<<cdiv(KDIM * 32, 256), 256>>>(W3, w3h, KDIM * 32);

    // ---- gcn_norm + CSR build ----
    deg_init_kernel<<<cdiv(n, 256), 256>>>(n);
    deg_acc_kernel<<<cdiv(E, 256), 256>>>(dstI, ew, E, n);
    dinv_kernel<<<cdiv(n, 256), 256>>>(n);
    scan_partial_kernel<<<nblk, 256>>>(n);
    scan_blocks_kernel<<<1, 128>>>(nblk, n);
    scan_final_kernel<<<nblk, 256>>>(n);
    scatter_kernel<<<cdiv(E, 256), 256>>>(srcI, dstI, ew, E, n);

    const int aggBlocks = cdiv(cdiv(n, 2) * 32, 256);

    // ---- layer 1: 128 -> 128, relu ----
    gemm_wmma_kernel<128><<<cdiv(n, 128), 256>>>(xh, w1h, n);
    agg_relu_kernel<<<aggBlocks, 256>>>(b1, n);

    // ---- layer 2: 128 -> 128, relu ----
    gemm_wmma_kernel<128><<<cdiv(n, 128), 256>>>(acth, w2h, n);
    agg_relu_kernel<<<aggBlocks, 256>>>(b2, n);

    // ---- layer 3: 128 -> 64, log_softmax ----
    gemm_wmma_kernel<64><<<cdiv(n, 128), 256>>>(acth, w3h, n);
    agg_lsm_kernel<<<aggBlocks, 256>>>(b3, outp, n);
}